// round 1
// baseline (speedup 1.0000x reference)
#include <cuda_runtime.h>
#include <cuda_bf16.h>
#include <math.h>

#define B_ 64
#define C_ 273
#define T_ 2048
#define O_ 256
#define D_ 2048
#define NF 32
#define MARGIN_F 0.2f
#define MTOT (B_*C_)      /* 17472 */
#define NPAD 17536        /* 548*32 == 137*128 */
#define CPAD 288          /* 273 padded to mult of 16 (and 9*32) */

// ---------------- scratch (static device globals; no allocation) ----------------
__device__ __align__(16) float g_ET[(size_t)D_ * NPAD];   // E^T, k-major: [k][bc]  (~143.7 MB)
__device__ __align__(16) float g_S [(size_t)O_ * MTOT];   // scores: [o][b*273+c]  (~17.9 MB)
__device__ __align__(16) float g_W [(size_t)B_ * O_ * CPAD]; // weights [b][o][cpad] (~18.9 MB)

__device__ __forceinline__ unsigned f2tf(float x){
    unsigned u; asm("cvt.rna.tf32.f32 %0, %1;" : "=r"(u) : "f"(x)); return u;
}
__device__ __forceinline__ float f2tff(float x){ return __uint_as_float(f2tf(x)); }

// ---------------- Kernel 0: build E^T (tf32-rounded fp32) ----------------
// E[row, i*32+j]        = cos(i*thx)*cos(j*thy) - sin(i*thx)*sin(j*thy)
// E[row, 1024+i*32+j]   = sin(i*thx)*cos(j*thy) + cos(i*thx)*sin(j*thy)
// where thx = (pos_x+margin)*2pi/width, thy likewise. Stored transposed: g_ET[k][row].
__global__ void etgen_kernel(const float* __restrict__ positions){
    __shared__ float tc[2][NF][NF];  // [which][i][r] , r innermost => conflict-free reads
    __shared__ float ts[2][NF][NF];
    int n0 = blockIdx.x * 32;
    int tid = threadIdx.x;           // 256 threads
    const float twopi_w = 6.28318530717958647692f / 1.4f;  // width = 1 + 2*margin
    #pragma unroll
    for (int u = 0; u < 8; u++){
        int idx   = tid + 256*u;     // 0..2047
        int which = idx >> 10;       // 0 = x-trig, 1 = y-trig
        int rem   = idx & 1023;
        int i     = rem >> 5;
        int r     = rem & 31;
        int n     = n0 + r;
        float c = 0.f, s = 0.f;
        if (n < MTOT){
            float p     = positions[2*n + which] + MARGIN_F;
            float theta = p * twopi_w;
            sincosf((float)i * theta, &s, &c);
        }
        tc[which][i][r] = c;
        ts[which][i][r] = s;
    }
    __syncthreads();
    int r  = tid & 31;
    int kb = tid >> 5;
    #pragma unroll 4
    for (int k = kb; k < D_; k += 8){
        int m = k & 1023;
        int i = m >> 5, j = m & 31;
        float cx = tc[0][i][r], sx = ts[0][i][r];
        float cy = tc[1][j][r], sy = ts[1][j][r];
        float v = (k < 1024) ? (cx*cy - sx*sy) : (sx*cy + cx*sy);
        g_ET[(size_t)k * NPAD + n0 + r] = f2tff(v);
    }
}

// ---------------- Generic TF32 GEMM: C[M,N] = A[M,K] (row) * B[K,N] (row) ----------------
// Block tile 128x128, BK=16, 256 threads = 8 warps (4 x 2), warp tile 32x64,
// mma.sync.m16n8k8 tf32, fp32 accumulate. Double-buffered smem.
// REQUIREMENTS (guaranteed by launcher): N-dim B loads never OOB (B buffer has
// gridDim.x*128 valid columns), K guard handled per-row, C stores guarded by (M,N).
#define BM 128
#define BN 128
#define BKT 16
#define AST 20    /* BK + 4  -> conflict-free A-frag LDS */
#define BST 136   /* BN + 8  -> conflict-free B-frag LDS */

__global__ void __launch_bounds__(256) gemm_tf32_kernel(
    const float* __restrict__ Ag, const float* __restrict__ Bg, float* __restrict__ Cg,
    int M, int N, int K, int lda, int ldb, int ldc,
    long long sA, long long sB, long long sC)
{
    __shared__ float As[2][BM][AST];
    __shared__ float Bs[2][BKT][BST];

    long long bz = blockIdx.z;
    const float* A = Ag + bz * sA;
    const float* B = Bg + bz * sB;
    float*       C = Cg + bz * sC;

    int n0 = blockIdx.x * BN;
    int m0 = blockIdx.y * BM;
    int tid  = threadIdx.x;
    int warp = tid >> 5, lane = tid & 31;
    int wm = (warp >> 1) * 32;   // warp row offset (4 warps in M)
    int wn = (warp & 1) * 64;    // warp col offset (2 warps in N)
    int g  = lane >> 2, tg = lane & 3;

    float acc[2][8][4];
    #pragma unroll
    for (int mt = 0; mt < 2; mt++)
        #pragma unroll
        for (int nt = 0; nt < 8; nt++)
            #pragma unroll
            for (int e = 0; e < 4; e++) acc[mt][nt][e] = 0.f;

    const bool fullM = (m0 + BM <= M);
    const int ar = tid >> 2;          // 0..63   (A row within half-tile)
    const int ac = (tid & 3) * 4;     // 0,4,8,12
    const int br = tid >> 5;          // 0..7    (B k-row within half-tile)
    const int bc = (tid & 31) * 4;    // 0..124

    int ktiles = (K + BKT - 1) / BKT;

    auto loadTile = [&](int buf, int k0){
        bool fullK = (k0 + BKT <= K);
        #pragma unroll
        for (int h = 0; h < 2; h++){
            int row = ar + h*64;
            long long gm = (long long)m0 + row;
            if (fullM && fullK){
                float4 v = *(const float4*)(A + gm*lda + k0 + ac);
                As[buf][row][ac+0] = f2tff(v.x);
                As[buf][row][ac+1] = f2tff(v.y);
                As[buf][row][ac+2] = f2tff(v.z);
                As[buf][row][ac+3] = f2tff(v.w);
            } else {
                #pragma unroll
                for (int e = 0; e < 4; e++){
                    int kk = k0 + ac + e;
                    float v = (gm < M && kk < K) ? A[gm*lda + kk] : 0.f;
                    As[buf][row][ac+e] = f2tff(v);
                }
            }
        }
        #pragma unroll
        for (int h = 0; h < 2; h++){
            int row = br + h*8;
            int gk  = k0 + row;
            if (gk < K){
                float4 v = *(const float4*)(B + (long long)gk*ldb + n0 + bc);
                Bs[buf][row][bc+0] = f2tff(v.x);
                Bs[buf][row][bc+1] = f2tff(v.y);
                Bs[buf][row][bc+2] = f2tff(v.z);
                Bs[buf][row][bc+3] = f2tff(v.w);
            } else {
                Bs[buf][row][bc+0] = 0.f;
                Bs[buf][row][bc+1] = 0.f;
                Bs[buf][row][bc+2] = 0.f;
                Bs[buf][row][bc+3] = 0.f;
            }
        }
    };

    loadTile(0, 0);
    __syncthreads();

    for (int kt = 0; kt < ktiles; kt++){
        int cur = kt & 1;
        if (kt + 1 < ktiles) loadTile(cur ^ 1, (kt + 1) * BKT);

        #pragma unroll
        for (int ks = 0; ks < 2; ks++){
            int k8 = ks * 8;
            unsigned a[2][4], bf[8][2];
            #pragma unroll
            for (int mt = 0; mt < 2; mt++){
                int rb = wm + 16*mt;
                a[mt][0] = __float_as_uint(As[cur][rb +     g][k8 + tg    ]);
                a[mt][1] = __float_as_uint(As[cur][rb + 8 + g][k8 + tg    ]);
                a[mt][2] = __float_as_uint(As[cur][rb +     g][k8 + tg + 4]);
                a[mt][3] = __float_as_uint(As[cur][rb + 8 + g][k8 + tg + 4]);
            }
            #pragma unroll
            for (int nt = 0; nt < 8; nt++){
                int cb = wn + 8*nt + g;
                bf[nt][0] = __float_as_uint(Bs[cur][k8 + tg    ][cb]);
                bf[nt][1] = __float_as_uint(Bs[cur][k8 + tg + 4][cb]);
            }
            #pragma unroll
            for (int mt = 0; mt < 2; mt++)
                #pragma unroll
                for (int nt = 0; nt < 8; nt++){
                    asm volatile(
                        "mma.sync.aligned.m16n8k8.row.col.f32.tf32.tf32.f32 "
                        "{%0,%1,%2,%3}, {%4,%5,%6,%7}, {%8,%9}, {%0,%1,%2,%3};"
                        : "+f"(acc[mt][nt][0]), "+f"(acc[mt][nt][1]),
                          "+f"(acc[mt][nt][2]), "+f"(acc[mt][nt][3])
                        : "r"(a[mt][0]), "r"(a[mt][1]), "r"(a[mt][2]), "r"(a[mt][3]),
                          "r"(bf[nt][0]), "r"(bf[nt][1]));
                }
        }
        __syncthreads();
    }

    // epilogue: D layout rows (g, g+8) x cols (2tg, 2tg+1)
    #pragma unroll
    for (int mt = 0; mt < 2; mt++){
        #pragma unroll
        for (int nt = 0; nt < 8; nt++){
            int row0 = m0 + wm + 16*mt + g;
            int col  = n0 + wn + 8*nt + 2*tg;
            if (col < N){
                if (row0 < M){
                    float2 v; v.x = acc[mt][nt][0]; v.y = acc[mt][nt][1];
                    *(float2*)(C + (long long)row0*ldc + col) = v;
                }
                int row1 = row0 + 8;
                if (row1 < M){
                    float2 v; v.x = acc[mt][nt][2]; v.y = acc[mt][nt][3];
                    *(float2*)(C + (long long)row1*ldc + col) = v;
                }
            }
        }
    }
}

// ---------------- Softmax over C: one warp per (b,o) ----------------
__global__ void softmax_kernel(const float* __restrict__ S,
                               const unsigned char* __restrict__ mask,
                               float* __restrict__ W)
{
    const float NEG_INF = __int_as_float(0xff800000);
    int idx  = blockIdx.x * 8 + (threadIdx.x >> 5);   // (b*256 + o)
    int lane = threadIdx.x & 31;
    int b = idx >> 8;
    int o = idx & 255;
    const float* row = S + (size_t)o * MTOT + (size_t)b * C_;
    const unsigned char* mrow = mask + (size_t)b * C_;

    float v[9];
    float vmax = NEG_INF;
    #pragma unroll
    for (int it = 0; it < 9; it++){
        int c = lane + 32*it;
        float s = NEG_INF;
        if (c < C_) s = mrow[c] ? NEG_INF : row[c];
        v[it] = s;
        vmax = fmaxf(vmax, s);
    }
    #pragma unroll
    for (int off = 16; off; off >>= 1)
        vmax = fmaxf(vmax, __shfl_xor_sync(0xffffffffu, vmax, off));

    float e[9];
    float sum = 0.f;
    #pragma unroll
    for (int it = 0; it < 9; it++){
        e[it] = __expf(v[it] - vmax);   // exp(-inf) -> 0 for masked / padded
        sum += e[it];
    }
    #pragma unroll
    for (int off = 16; off; off >>= 1)
        sum += __shfl_xor_sync(0xffffffffu, sum, off);

    float inv = 1.f / sum;
    float* wrow = W + ((size_t)b * O_ + o) * CPAD;
    #pragma unroll
    for (int it = 0; it < 9; it++){
        int c = lane + 32*it;           // covers exactly 0..287
        wrow[c] = (c < C_) ? e[it] * inv : 0.f;
    }
}

// ---------------- launcher ----------------
extern "C" void kernel_launch(void* const* d_in, const int* in_sizes, int n_in,
                              void* d_out, int out_size)
{
    const float* x = nullptr;
    const float* positions = nullptr;
    const unsigned char* mask = nullptr;
    const float* heads = nullptr;
    for (int i = 0; i < n_in; i++){
        long long s = in_sizes[i];
        if      (s == (long long)B_*C_*T_) x         = (const float*)d_in[i];
        else if (s == (long long)B_*C_*2 ) positions = (const float*)d_in[i];
        else if (s == (long long)B_*C_   ) mask      = (const unsigned char*)d_in[i];
        else if (s == (long long)O_*D_   ) heads     = (const float*)d_in[i];
    }

    float *pET, *pS, *pW;
    cudaGetSymbolAddress((void**)&pET, g_ET);
    cudaGetSymbolAddress((void**)&pS,  g_S);
    cudaGetSymbolAddress((void**)&pW,  g_W);

    // 1) Fourier embedding, transposed + tf32-rounded
    etgen_kernel<<<NPAD/32, 256>>>(positions);

    // 2) scores[o][bc] = heads[o,:] . E[bc,:]   (M=256, N=17472, K=2048)
    gemm_tf32_kernel<<<dim3(NPAD/BN, O_/BM, 1), 256>>>(
        heads, pET, pS,
        O_, MTOT, D_,
        D_, NPAD, MTOT,
        0, 0, 0);

    // 3) softmax over c -> weights [b][o][cpad]
    softmax_kernel<<<(B_*O_)/8, 256>>>(pS, mask, pW);

    // 4) out[b] = W[b] (256 x 273) * x[b] (273 x 2048), batched over b
    gemm_tf32_kernel<<<dim3(T_/BN, O_/BM, B_), 256>>>(
        pW, x, (float*)d_out,
        O_, T_, C_,
        CPAD, T_, T_,
        (long long)O_*CPAD, (long long)C_*T_, (long long)O_*T_);
}

// round 2
// speedup vs baseline: 1.0121x; 1.0121x over previous
#include <cuda_runtime.h>
#include <cuda_bf16.h>
#include <math.h>

#define B_ 64
#define C_ 273
#define T_ 2048
#define O_ 256
#define D_ 2048
#define NF 32
#define MARGIN_F 0.2f
#define MTOT (B_*C_)      /* 17472 */
#define NPAD 17536        /* 548*32 == 137*128 */
#define CPAD 288          /* 273 padded to mult of 16 (and 9*32) */

// ---------------- scratch (static device globals; no allocation) ----------------
__device__ __align__(16) float g_ET[(size_t)D_ * NPAD];   // E^T, k-major: [k][bc]  (~143.7 MB)
__device__ __align__(16) float g_S [(size_t)O_ * MTOT];   // scores: [o][b*273+c]  (~17.9 MB)
__device__ __align__(16) float g_W [(size_t)B_ * O_ * CPAD]; // weights [b][o][cpad] (~18.9 MB)

__device__ __forceinline__ unsigned f2tf(float x){
    unsigned u; asm("cvt.rna.tf32.f32 %0, %1;" : "=r"(u) : "f"(x)); return u;
}
__device__ __forceinline__ float f2tff(float x){ return __uint_as_float(f2tf(x)); }

// ---------------- Kernel 0: build E^T (tf32-rounded fp32) ----------------
// E[row, i*32+j]        = cos(i*thx)*cos(j*thy) - sin(i*thx)*sin(j*thy)
// E[row, 1024+i*32+j]   = sin(i*thx)*cos(j*thy) + cos(i*thx)*sin(j*thy)
// where thx = (pos_x+margin)*2pi/width, thy likewise. Stored transposed: g_ET[k][row].
__global__ void etgen_kernel(const float* __restrict__ positions){
    __shared__ float tc[2][NF][NF];  // [which][i][r] , r innermost => conflict-free reads
    __shared__ float ts[2][NF][NF];
    int n0 = blockIdx.x * 32;
    int tid = threadIdx.x;           // 256 threads
    const float twopi_w = 6.28318530717958647692f / 1.4f;  // width = 1 + 2*margin
    #pragma unroll
    for (int u = 0; u < 8; u++){
        int idx   = tid + 256*u;     // 0..2047
        int which = idx >> 10;       // 0 = x-trig, 1 = y-trig
        int rem   = idx & 1023;
        int i     = rem >> 5;
        int r     = rem & 31;
        int n     = n0 + r;
        float c = 0.f, s = 0.f;
        if (n < MTOT){
            float p     = positions[2*n + which] + MARGIN_F;
            float theta = p * twopi_w;
            sincosf((float)i * theta, &s, &c);
        }
        tc[which][i][r] = c;
        ts[which][i][r] = s;
    }
    __syncthreads();
    int r  = tid & 31;
    int kb = tid >> 5;
    #pragma unroll 4
    for (int k = kb; k < D_; k += 8){
        int m = k & 1023;
        int i = m >> 5, j = m & 31;
        float cx = tc[0][i][r], sx = ts[0][i][r];
        float cy = tc[1][j][r], sy = ts[1][j][r];
        float v = (k < 1024) ? (cx*cy - sx*sy) : (sx*cy + cx*sy);
        g_ET[(size_t)k * NPAD + n0 + r] = f2tff(v);
    }
}

// ---------------- Generic TF32 GEMM: C[M,N] = A[M,K] (row) * B[K,N] (row) ----------------
// Block tile 128x128, BK=16, 256 threads = 8 warps (4 x 2), warp tile 32x64,
// mma.sync.m16n8k8 tf32, fp32 accumulate. Double-buffered smem.
// REQUIREMENTS (guaranteed by launcher): N-dim B loads never OOB (B buffer has
// gridDim.x*128 valid columns), K guard handled per-row, C stores guarded by (M,N).
#define BM 128
#define BN 128
#define BKT 16
#define AST 20    /* BK + 4  -> conflict-free A-frag LDS */
#define BST 136   /* BN + 8  -> conflict-free B-frag LDS */

__global__ void __launch_bounds__(256) gemm_tf32_kernel(
    const float* __restrict__ Ag, const float* __restrict__ Bg, float* __restrict__ Cg,
    int M, int N, int K, int lda, int ldb, int ldc,
    long long sA, long long sB, long long sC)
{
    __shared__ float As[2][BM][AST];
    __shared__ float Bs[2][BKT][BST];

    long long bz = blockIdx.z;
    const float* A = Ag + bz * sA;
    const float* B = Bg + bz * sB;
    float*       C = Cg + bz * sC;

    int n0 = blockIdx.x * BN;
    int m0 = blockIdx.y * BM;
    int tid  = threadIdx.x;
    int warp = tid >> 5, lane = tid & 31;
    int wm = (warp >> 1) * 32;   // warp row offset (4 warps in M)
    int wn = (warp & 1) * 64;    // warp col offset (2 warps in N)
    int g  = lane >> 2, tg = lane & 3;

    float acc[2][8][4];
    #pragma unroll
    for (int mt = 0; mt < 2; mt++)
        #pragma unroll
        for (int nt = 0; nt < 8; nt++)
            #pragma unroll
            for (int e = 0; e < 4; e++) acc[mt][nt][e] = 0.f;

    const bool fullM = (m0 + BM <= M);
    const int ar = tid >> 2;          // 0..63   (A row within half-tile)
    const int ac = (tid & 3) * 4;     // 0,4,8,12
    const int br = tid >> 5;          // 0..7    (B k-row within half-tile)
    const int bc = (tid & 31) * 4;    // 0..124

    int ktiles = (K + BKT - 1) / BKT;

    auto loadTile = [&](int buf, int k0){
        bool fullK = (k0 + BKT <= K);
        #pragma unroll
        for (int h = 0; h < 2; h++){
            int row = ar + h*64;
            long long gm = (long long)m0 + row;
            if (fullM && fullK){
                float4 v = *(const float4*)(A + gm*lda + k0 + ac);
                As[buf][row][ac+0] = f2tff(v.x);
                As[buf][row][ac+1] = f2tff(v.y);
                As[buf][row][ac+2] = f2tff(v.z);
                As[buf][row][ac+3] = f2tff(v.w);
            } else {
                #pragma unroll
                for (int e = 0; e < 4; e++){
                    int kk = k0 + ac + e;
                    float v = (gm < M && kk < K) ? A[gm*lda + kk] : 0.f;
                    As[buf][row][ac+e] = f2tff(v);
                }
            }
        }
        #pragma unroll
        for (int h = 0; h < 2; h++){
            int row = br + h*8;
            int gk  = k0 + row;
            if (gk < K){
                float4 v = *(const float4*)(B + (long long)gk*ldb + n0 + bc);
                Bs[buf][row][bc+0] = f2tff(v.x);
                Bs[buf][row][bc+1] = f2tff(v.y);
                Bs[buf][row][bc+2] = f2tff(v.z);
                Bs[buf][row][bc+3] = f2tff(v.w);
            } else {
                Bs[buf][row][bc+0] = 0.f;
                Bs[buf][row][bc+1] = 0.f;
                Bs[buf][row][bc+2] = 0.f;
                Bs[buf][row][bc+3] = 0.f;
            }
        }
    };

    loadTile(0, 0);
    __syncthreads();

    for (int kt = 0; kt < ktiles; kt++){
        int cur = kt & 1;
        if (kt + 1 < ktiles) loadTile(cur ^ 1, (kt + 1) * BKT);

        #pragma unroll
        for (int ks = 0; ks < 2; ks++){
            int k8 = ks * 8;
            unsigned a[2][4], bf[8][2];
            #pragma unroll
            for (int mt = 0; mt < 2; mt++){
                int rb = wm + 16*mt;
                a[mt][0] = __float_as_uint(As[cur][rb +     g][k8 + tg    ]);
                a[mt][1] = __float_as_uint(As[cur][rb + 8 + g][k8 + tg    ]);
                a[mt][2] = __float_as_uint(As[cur][rb +     g][k8 + tg + 4]);
                a[mt][3] = __float_as_uint(As[cur][rb + 8 + g][k8 + tg + 4]);
            }
            #pragma unroll
            for (int nt = 0; nt < 8; nt++){
                int cb = wn + 8*nt + g;
                bf[nt][0] = __float_as_uint(Bs[cur][k8 + tg    ][cb]);
                bf[nt][1] = __float_as_uint(Bs[cur][k8 + tg + 4][cb]);
            }
            #pragma unroll
            for (int mt = 0; mt < 2; mt++)
                #pragma unroll
                for (int nt = 0; nt < 8; nt++){
                    asm volatile(
                        "mma.sync.aligned.m16n8k8.row.col.f32.tf32.tf32.f32 "
                        "{%0,%1,%2,%3}, {%4,%5,%6,%7}, {%8,%9}, {%0,%1,%2,%3};"
                        : "+f"(acc[mt][nt][0]), "+f"(acc[mt][nt][1]),
                          "+f"(acc[mt][nt][2]), "+f"(acc[mt][nt][3])
                        : "r"(a[mt][0]), "r"(a[mt][1]), "r"(a[mt][2]), "r"(a[mt][3]),
                          "r"(bf[nt][0]), "r"(bf[nt][1]));
                }
        }
        __syncthreads();
    }

    // epilogue: D layout rows (g, g+8) x cols (2tg, 2tg+1)
    #pragma unroll
    for (int mt = 0; mt < 2; mt++){
        #pragma unroll
        for (int nt = 0; nt < 8; nt++){
            int row0 = m0 + wm + 16*mt + g;
            int col  = n0 + wn + 8*nt + 2*tg;
            if (col < N){
                if (row0 < M){
                    float2 v; v.x = acc[mt][nt][0]; v.y = acc[mt][nt][1];
                    *(float2*)(C + (long long)row0*ldc + col) = v;
                }
                int row1 = row0 + 8;
                if (row1 < M){
                    float2 v; v.x = acc[mt][nt][2]; v.y = acc[mt][nt][3];
                    *(float2*)(C + (long long)row1*ldc + col) = v;
                }
            }
        }
    }
}

// ---------------- Softmax over C: one warp per (b,o) ----------------
__global__ void softmax_kernel(const float* __restrict__ S,
                               const unsigned char* __restrict__ mask,
                               float* __restrict__ W)
{
    const float NEG_INF = __int_as_float(0xff800000);
    int idx  = blockIdx.x * 8 + (threadIdx.x >> 5);   // (b*256 + o)
    int lane = threadIdx.x & 31;
    int b = idx >> 8;
    int o = idx & 255;
    const float* row = S + (size_t)o * MTOT + (size_t)b * C_;
    const unsigned char* mrow = mask + (size_t)b * C_;

    float v[9];
    float vmax = NEG_INF;
    #pragma unroll
    for (int it = 0; it < 9; it++){
        int c = lane + 32*it;
        float s = NEG_INF;
        if (c < C_) s = mrow[c] ? NEG_INF : row[c];
        v[it] = s;
        vmax = fmaxf(vmax, s);
    }
    #pragma unroll
    for (int off = 16; off; off >>= 1)
        vmax = fmaxf(vmax, __shfl_xor_sync(0xffffffffu, vmax, off));

    float e[9];
    float sum = 0.f;
    #pragma unroll
    for (int it = 0; it < 9; it++){
        e[it] = __expf(v[it] - vmax);   // exp(-inf) -> 0 for masked / padded
        sum += e[it];
    }
    #pragma unroll
    for (int off = 16; off; off >>= 1)
        sum += __shfl_xor_sync(0xffffffffu, sum, off);

    float inv = 1.f / sum;
    float* wrow = W + ((size_t)b * O_ + o) * CPAD;
    #pragma unroll
    for (int it = 0; it < 9; it++){
        int c = lane + 32*it;           // covers exactly 0..287
        wrow[c] = (c < C_) ? e[it] * inv : 0.f;
    }
}

// ---------------- launcher ----------------
extern "C" void kernel_launch(void* const* d_in, const int* in_sizes, int n_in,
                              void* d_out, int out_size)
{
    const float* x = nullptr;
    const float* positions = nullptr;
    const unsigned char* mask = nullptr;
    const float* heads = nullptr;
    for (int i = 0; i < n_in; i++){
        long long s = in_sizes[i];
        if      (s == (long long)B_*C_*T_) x         = (const float*)d_in[i];
        else if (s == (long long)B_*C_*2 ) positions = (const float*)d_in[i];
        else if (s == (long long)B_*C_   ) mask      = (const unsigned char*)d_in[i];
        else if (s == (long long)O_*D_   ) heads     = (const float*)d_in[i];
    }

    float *pET, *pS, *pW;
    cudaGetSymbolAddress((void**)&pET, g_ET);
    cudaGetSymbolAddress((void**)&pS,  g_S);
    cudaGetSymbolAddress((void**)&pW,  g_W);

    // 1) Fourier embedding, transposed + tf32-rounded
    etgen_kernel<<<NPAD/32, 256>>>(positions);

    // 2) scores[o][bc] = heads[o,:] . E[bc,:]   (M=256, N=17472, K=2048)
    gemm_tf32_kernel<<<dim3(NPAD/BN, O_/BM, 1), 256>>>(
        heads, pET, pS,
        O_, MTOT, D_,
        D_, NPAD, MTOT,
        0, 0, 0);

    // 3) softmax over c -> weights [b][o][cpad]
    softmax_kernel<<<(B_*O_)/8, 256>>>(pS, mask, pW);

    // 4) out[b] = W[b] (256 x 273) * x[b] (273 x 2048), batched over b
    gemm_tf32_kernel<<<dim3(T_/BN, O_/BM, B_), 256>>>(
        pW, x, (float*)d_out,
        O_, T_, C_,
        CPAD, T_, T_,
        (long long)O_*CPAD, (long long)C_*T_, (long long)O_*T_);
}

// round 3
// speedup vs baseline: 1.6640x; 1.6440x over previous
#include <cuda_runtime.h>
#include <cuda_bf16.h>
#include <math.h>

#define B_ 64
#define C_ 273
#define T_ 2048
#define O_ 256
#define D_ 2048
#define NF 32
#define MARGIN_F 0.2f
#define MTOT (B_*C_)      /* 17472 */
#define NPAD 17536        /* 137*128 */
#define CPAD 288          /* 273 -> mult of 16 */

// ---------------- scratch (static device globals; no allocation) ----------------
__device__ __align__(16) float g_ET[(size_t)D_ * NPAD];     // E^T k-major [k][bc]
__device__ __align__(16) float g_hT[(size_t)D_ * O_];       // heads^T k-major [d][o]
__device__ __align__(16) float g_S [(size_t)O_ * MTOT];     // scores [o][b*273+c]
__device__ __align__(16) float g_W [(size_t)B_ * O_ * CPAD];// weights [b][o][cpad]
__device__ __align__(16) float g_Wt[(size_t)B_ * CPAD * O_];// weights^T [b][cpad][o]

__device__ __forceinline__ unsigned f2tf(float x){
    unsigned u; asm("cvt.rna.tf32.f32 %0, %1;" : "=r"(u) : "f"(x)); return u;
}
__device__ __forceinline__ float f2tff(float x){ return __uint_as_float(f2tf(x)); }

// ---------------- Kernel 0: build E^T (tf32-rounded) ----------------
__global__ void etgen_kernel(const float* __restrict__ positions){
    __shared__ float tc[2][NF][NF];
    __shared__ float ts[2][NF][NF];
    int n0 = blockIdx.x * 32;
    int tid = threadIdx.x;           // 256 threads
    const float twopi_w = 6.28318530717958647692f / 1.4f;
    #pragma unroll
    for (int u = 0; u < 8; u++){
        int idx   = tid + 256*u;
        int which = idx >> 10;
        int rem   = idx & 1023;
        int i     = rem >> 5;
        int r     = rem & 31;
        int n     = n0 + r;
        float c = 0.f, s = 0.f;
        if (n < MTOT){
            float p     = positions[2*n + which] + MARGIN_F;
            float theta = p * twopi_w;
            sincosf((float)i * theta, &s, &c);
        }
        tc[which][i][r] = c;
        ts[which][i][r] = s;
    }
    __syncthreads();
    int r  = tid & 31;
    int kb = tid >> 5;
    #pragma unroll 4
    for (int k = kb; k < D_; k += 8){
        int m = k & 1023;
        int i = m >> 5, j = m & 31;
        float cx = tc[0][i][r], sx = ts[0][i][r];
        float cy = tc[1][j][r], sy = ts[1][j][r];
        float v = (k < 1024) ? (cx*cy - sx*sy) : (sx*cy + cx*sy);
        g_ET[(size_t)k * NPAD + n0 + r] = f2tff(v);
    }
}

// ---------------- transpose (+tf32 round): out[c][r] = round(in[r][c]) ----------------
__global__ void transpose_round_kernel(const float* __restrict__ in, float* __restrict__ out,
                                       int R, int Cc, long long sIn, long long sOut)
{
    __shared__ float t[32][33];
    long long bz = blockIdx.z;
    const float* I = in + bz*sIn;
    float* Ot = out + bz*sOut;
    int c0 = blockIdx.x*32, r0 = blockIdx.y*32;
    int tx = threadIdx.x, ty = threadIdx.y;  // 32 x 8
    #pragma unroll
    for (int i = 0; i < 4; i++){
        int r = r0 + ty + 8*i, c = c0 + tx;
        float v = (r < R && c < Cc) ? I[(long long)r*Cc + c] : 0.f;
        t[ty+8*i][tx] = f2tff(v);
    }
    __syncthreads();
    #pragma unroll
    for (int i = 0; i < 4; i++){
        int r = r0 + tx, c = c0 + ty + 8*i;
        if (c < Cc && r < R) Ot[(long long)c*R + r] = t[tx][ty+8*i];
    }
}

// ---------------- TN GEMM, cp.async 4-stage, vectorized fragments ----------------
// C[M,N] = sum_k At[k][m] * B[k][n]; At,B K-major. M mult of 128 (no row guard on loads),
// N-columns of B always in-bounds (launcher guarantees buffer padding), C stores guarded.
#define BK 16
#define AP 136
#define BP 136
#define TILEA (BK*AP)
#define TILEB (BK*BP)
#define STG_FLOATS (TILEA + TILEB)
#define STAGES 4
#define GEMM_SMEM (STAGES * STG_FLOATS * 4)

__device__ __forceinline__ void cp_commit(){ asm volatile("cp.async.commit_group;\n"::); }
template<int N_> __device__ __forceinline__ void cp_wait(){ asm volatile("cp.async.wait_group %0;\n"::"n"(N_)); }
__device__ __forceinline__ void cpa16(float* dst, const float* src, bool pred){
    unsigned d = (unsigned)__cvta_generic_to_shared(dst);
    int sz = pred ? 16 : 0;
    asm volatile("cp.async.cg.shared.global [%0], [%1], 16, %2;\n" :: "r"(d), "l"(src), "r"(sz));
}

template<bool CVTB>
__global__ void __launch_bounds__(256) gemm_tn(
    const float* __restrict__ Atg, const float* __restrict__ Bg, float* __restrict__ Cg,
    int M, int N, int K, int Kb, int lda, int ldb, int ldc,
    long long sA, long long sB, long long sC)
{
    extern __shared__ float sm[];
    long long bz = blockIdx.z;
    const float* At = Atg + bz*sA;
    const float* B  = Bg  + bz*sB;
    float*       C  = Cg  + bz*sC;

    int n0 = blockIdx.x * 128;
    int m0 = blockIdx.y * 128;
    int tid  = threadIdx.x;
    int warp = tid >> 5, lane = tid & 31;
    int g = lane >> 2, tg = lane & 3;
    int wm = (warp >> 1) * 32;
    int wn = (warp & 1) * 64;

    float acc[2][8][4];
    #pragma unroll
    for (int mt = 0; mt < 2; mt++)
        #pragma unroll
        for (int nt = 0; nt < 8; nt++)
            #pragma unroll
            for (int e = 0; e < 4; e++) acc[mt][nt][e] = 0.f;

    const int ktiles = K / BK;

    auto load_stage = [&](int s, int kt){
        float* dA = sm + s * STG_FLOATS;
        float* dB = dA + TILEA;
        int k0 = kt * BK;
        #pragma unroll
        for (int j = 0; j < 2; j++){
            int id = tid + 256*j;
            int r = id >> 5, cm = (id & 31) * 4;
            cpa16(dA + r*AP + cm, At + (long long)(k0+r)*lda + m0 + cm, (k0+r) < K);
        }
        #pragma unroll
        for (int j = 0; j < 2; j++){
            int id = tid + 256*j;
            int r = id >> 5, cn = (id & 31) * 4;
            cpa16(dB + r*BP + cn, B + (long long)(k0+r)*ldb + n0 + cn, (k0+r) < Kb);
        }
        cp_commit();
    };

    // prologue: STAGES-1 tiles in flight (ktiles >= 3 by construction)
    load_stage(0, 0);
    load_stage(1, 1);
    load_stage(2, 2);

    for (int kt = 0; kt < ktiles; kt++){
        cp_wait<STAGES-2>();
        __syncthreads();
        if (kt + STAGES - 1 < ktiles) load_stage((kt + STAGES - 1) % STAGES, kt + STAGES - 1);
        else                          cp_commit();

        const float* dA = sm + (kt % STAGES) * STG_FLOATS;
        const float* dB = dA + TILEA;

        #pragma unroll
        for (int ks = 0; ks < 2; ks++){
            int k0 = ks*8 + tg;
            float4 a0  = *(const float4*)(dA + (k0  )*AP + wm + 4*g);
            float4 a1  = *(const float4*)(dA + (k0+4)*AP + wm + 4*g);
            float4 b00 = *(const float4*)(dB + (k0  )*BP + wn + 8*g);
            float4 b01 = *(const float4*)(dB + (k0  )*BP + wn + 8*g + 4);
            float4 b10 = *(const float4*)(dB + (k0+4)*BP + wn + 8*g);
            float4 b11 = *(const float4*)(dB + (k0+4)*BP + wn + 8*g + 4);

            unsigned ua[2][4];
            ua[0][0]=__float_as_uint(a0.x); ua[1][0]=__float_as_uint(a0.y);
            ua[0][1]=__float_as_uint(a0.z); ua[1][1]=__float_as_uint(a0.w);
            ua[0][2]=__float_as_uint(a1.x); ua[1][2]=__float_as_uint(a1.y);
            ua[0][3]=__float_as_uint(a1.z); ua[1][3]=__float_as_uint(a1.w);

            unsigned ub[8][2];
            if (CVTB){
                ub[0][0]=f2tf(b00.x); ub[1][0]=f2tf(b00.y); ub[2][0]=f2tf(b00.z); ub[3][0]=f2tf(b00.w);
                ub[4][0]=f2tf(b01.x); ub[5][0]=f2tf(b01.y); ub[6][0]=f2tf(b01.z); ub[7][0]=f2tf(b01.w);
                ub[0][1]=f2tf(b10.x); ub[1][1]=f2tf(b10.y); ub[2][1]=f2tf(b10.z); ub[3][1]=f2tf(b10.w);
                ub[4][1]=f2tf(b11.x); ub[5][1]=f2tf(b11.y); ub[6][1]=f2tf(b11.z); ub[7][1]=f2tf(b11.w);
            } else {
                ub[0][0]=__float_as_uint(b00.x); ub[1][0]=__float_as_uint(b00.y);
                ub[2][0]=__float_as_uint(b00.z); ub[3][0]=__float_as_uint(b00.w);
                ub[4][0]=__float_as_uint(b01.x); ub[5][0]=__float_as_uint(b01.y);
                ub[6][0]=__float_as_uint(b01.z); ub[7][0]=__float_as_uint(b01.w);
                ub[0][1]=__float_as_uint(b10.x); ub[1][1]=__float_as_uint(b10.y);
                ub[2][1]=__float_as_uint(b10.z); ub[3][1]=__float_as_uint(b10.w);
                ub[4][1]=__float_as_uint(b11.x); ub[5][1]=__float_as_uint(b11.y);
                ub[6][1]=__float_as_uint(b11.z); ub[7][1]=__float_as_uint(b11.w);
            }

            #pragma unroll
            for (int mt = 0; mt < 2; mt++)
                #pragma unroll
                for (int nt = 0; nt < 8; nt++){
                    asm volatile(
                        "mma.sync.aligned.m16n8k8.row.col.f32.tf32.tf32.f32 "
                        "{%0,%1,%2,%3}, {%4,%5,%6,%7}, {%8,%9}, {%0,%1,%2,%3};"
                        : "+f"(acc[mt][nt][0]), "+f"(acc[mt][nt][1]),
                          "+f"(acc[mt][nt][2]), "+f"(acc[mt][nt][3])
                        : "r"(ua[mt][0]), "r"(ua[mt][1]), "r"(ua[mt][2]), "r"(ua[mt][3]),
                          "r"(ub[nt][0]), "r"(ub[nt][1]));
                }
        }
        __syncthreads();
    }

    // epilogue: thread owns rows {m0+wm+4g+2h+mt}, 16 contiguous cols at n0+wn+16tg
    int cb = n0 + wn + 16*tg;
    #pragma unroll
    for (int mt = 0; mt < 2; mt++){
        #pragma unroll
        for (int h = 0; h < 2; h++){
            int row = m0 + wm + 4*g + 2*h + mt;
            if (row < M){
                float* Cr = C + (long long)row*ldc;
                float4 v0, v1, v2, v3;
                v0.x=acc[mt][0][2*h];   v0.y=acc[mt][1][2*h];   v0.z=acc[mt][2][2*h];   v0.w=acc[mt][3][2*h];
                v1.x=acc[mt][4][2*h];   v1.y=acc[mt][5][2*h];   v1.z=acc[mt][6][2*h];   v1.w=acc[mt][7][2*h];
                v2.x=acc[mt][0][2*h+1]; v2.y=acc[mt][1][2*h+1]; v2.z=acc[mt][2][2*h+1]; v2.w=acc[mt][3][2*h+1];
                v3.x=acc[mt][4][2*h+1]; v3.y=acc[mt][5][2*h+1]; v3.z=acc[mt][6][2*h+1]; v3.w=acc[mt][7][2*h+1];
                if (cb      < N) *(float4*)(Cr + cb     ) = v0;
                if (cb + 4  < N) *(float4*)(Cr + cb + 4 ) = v1;
                if (cb + 8  < N) *(float4*)(Cr + cb + 8 ) = v2;
                if (cb + 12 < N) *(float4*)(Cr + cb + 12) = v3;
            }
        }
    }
}

// ---------------- softmax over C: one warp per (b,o) ----------------
__global__ void softmax_kernel(const float* __restrict__ S,
                               const unsigned char* __restrict__ mask,
                               float* __restrict__ W)
{
    const float NEG_INF = __int_as_float(0xff800000);
    int idx  = blockIdx.x * 8 + (threadIdx.x >> 5);
    int lane = threadIdx.x & 31;
    int b = idx >> 8;
    int o = idx & 255;
    const float* row = S + (size_t)o * MTOT + (size_t)b * C_;
    const unsigned char* mrow = mask + (size_t)b * C_;

    float v[9];
    float vmax = NEG_INF;
    #pragma unroll
    for (int it = 0; it < 9; it++){
        int c = lane + 32*it;
        float s = NEG_INF;
        if (c < C_) s = mrow[c] ? NEG_INF : row[c];
        v[it] = s;
        vmax = fmaxf(vmax, s);
    }
    #pragma unroll
    for (int off = 16; off; off >>= 1)
        vmax = fmaxf(vmax, __shfl_xor_sync(0xffffffffu, vmax, off));

    float e[9];
    float sum = 0.f;
    #pragma unroll
    for (int it = 0; it < 9; it++){
        e[it] = __expf(v[it] - vmax);
        sum += e[it];
    }
    #pragma unroll
    for (int off = 16; off; off >>= 1)
        sum += __shfl_xor_sync(0xffffffffu, sum, off);

    float inv = 1.f / sum;
    float* wrow = W + ((size_t)b * O_ + o) * CPAD;
    #pragma unroll
    for (int it = 0; it < 9; it++){
        int c = lane + 32*it;
        wrow[c] = (c < C_) ? e[it] * inv : 0.f;
    }
}

// ---------------- launcher ----------------
extern "C" void kernel_launch(void* const* d_in, const int* in_sizes, int n_in,
                              void* d_out, int out_size)
{
    const float* x = nullptr;
    const float* positions = nullptr;
    const unsigned char* mask = nullptr;
    const float* heads = nullptr;
    for (int i = 0; i < n_in; i++){
        long long s = in_sizes[i];
        if      (s == (long long)B_*C_*T_) x         = (const float*)d_in[i];
        else if (s == (long long)B_*C_*2 ) positions = (const float*)d_in[i];
        else if (s == (long long)B_*C_   ) mask      = (const unsigned char*)d_in[i];
        else if (s == (long long)O_*D_   ) heads     = (const float*)d_in[i];
    }

    float *pET, *pHT, *pS, *pW, *pWt;
    cudaGetSymbolAddress((void**)&pET, g_ET);
    cudaGetSymbolAddress((void**)&pHT, g_hT);
    cudaGetSymbolAddress((void**)&pS,  g_S);
    cudaGetSymbolAddress((void**)&pW,  g_W);
    cudaGetSymbolAddress((void**)&pWt, g_Wt);

    cudaFuncSetAttribute(gemm_tn<false>, cudaFuncAttributeMaxDynamicSharedMemorySize, GEMM_SMEM);
    cudaFuncSetAttribute(gemm_tn<true>,  cudaFuncAttributeMaxDynamicSharedMemorySize, GEMM_SMEM);

    // 1) Fourier embedding E^T (tf32-rounded)
    etgen_kernel<<<NPAD/32, 256>>>(positions);

    // 1b) heads^T (tf32-rounded): [2048][256]
    transpose_round_kernel<<<dim3(D_/32, O_/32, 1), dim3(32,8)>>>(
        heads, pHT, O_, D_, 0, 0);

    // 2) scores[o][bc]: M=256, N=17472, K=2048 (all operands pre-rounded)
    gemm_tn<false><<<dim3(NPAD/128, O_/128, 1), 256, GEMM_SMEM>>>(
        pHT, pET, pS,
        O_, MTOT, D_, D_,
        O_, NPAD, MTOT,
        0, 0, 0);

    // 3) softmax -> W [b][o][cpad]
    softmax_kernel<<<(B_*O_)/8, 256>>>(pS, mask, pW);

    // 3b) W^T per batch (tf32-rounded): [b][cpad][o]
    transpose_round_kernel<<<dim3(CPAD/32, O_/32, B_), dim3(32,8)>>>(
        pW, pWt, O_, CPAD,
        (long long)O_*CPAD, (long long)CPAD*O_);

    // 4) out[b] = W[b] @ x[b]: M=256, N=2048, K=288 (Kb=273), batched over b
    gemm_tn<true><<<dim3(T_/128, O_/128, B_), 256, GEMM_SMEM>>>(
        pWt, x, (float*)d_out,
        O_, T_, CPAD, C_,
        O_, T_, T_,
        (long long)CPAD*O_, (long long)C_*T_, (long long)O_*T_);
}